// round 16
// baseline (speedup 1.0000x reference)
#include <cuda_runtime.h>
#include <cuda_bf16.h>
#include <cstdint>

#define NN 50000
#define NE 800000
#define KIN 166
#define HID 128
#define BN_EPS 1e-5f
#define SCAN_B 256
#define NBLK ((NN + SCAN_B - 1) / SCAN_B)   // 196
#define GEMM_SMEM (4 * 128 * 368)           // 188416 B (max K path)

// ---------------------------------------------------------------------------
// Scratch (device globals — no allocation allowed). 16B-aligned for vector ld/st.
// ---------------------------------------------------------------------------
__device__ __align__(16) float g_y  [NN * HID];
__device__ __align__(16) float g_r  [NN * HID];
__device__ __align__(16) float g_p  [NN * HID];
__device__ __align__(16) float g_h0 [NN * HID];
__device__ __align__(16) float g_h1 [NN * HID];
__device__ float g_inv[NN];
__device__ int   g_deg[NN];
__device__ int   g_rowstart[NN + 1];
__device__ int   g_cursor[NN];
__device__ int   g_csrc[NE];
__device__ __align__(16) float g_z2[NN * 2];
__device__ int   g_is64;
__device__ int   g_bsum[NBLK];
__device__ int   g_boff[NBLK];

// ---------------------------------------------------------------------------
// Warp-level tensor core helpers (baseline PTX: sm_80+ features, compile OK
// at compute_103 — tcgen05 does NOT, it needs the 'a' virtual arch).
// ---------------------------------------------------------------------------
__device__ __forceinline__ uint32_t smem_u32(const void* p) {
    uint32_t a;
    asm("{ .reg .u64 tmp; cvta.to.shared.u64 tmp, %1; cvt.u32.u64 %0, tmp; }"
        : "=r"(a) : "l"(p));
    return a;
}
__device__ __forceinline__ void ldsm4(uint32_t* r, uint32_t addr) {
    asm volatile("ldmatrix.sync.aligned.m8n8.x4.shared.b16 {%0,%1,%2,%3}, [%4];"
        : "=r"(r[0]), "=r"(r[1]), "=r"(r[2]), "=r"(r[3]) : "r"(addr));
}
__device__ __forceinline__ void mma_bf16(float* d, const uint32_t* a,
                                         uint32_t b0, uint32_t b1) {
    asm volatile(
        "mma.sync.aligned.m16n8k16.row.col.f32.bf16.bf16.f32 "
        "{%0,%1,%2,%3}, {%4,%5,%6,%7}, {%8,%9}, {%0,%1,%2,%3};"
        : "+f"(d[0]), "+f"(d[1]), "+f"(d[2]), "+f"(d[3])
        : "r"(a[0]), "r"(a[1]), "r"(a[2]), "r"(a[3]), "r"(b0), "r"(b1));
}

// ---------------------------------------------------------------------------
// Edge dtype detection
// ---------------------------------------------------------------------------
__global__ void detect_k(const void* ei_raw) {
    const long long* p = (const long long*)ei_raw;
    int lane = threadIdx.x;
    int ok = 1;
#pragma unroll
    for (int i = 0; i < 16; i++) {
        long long v = p[lane * 16 + i];
        if (v < 0 || v >= NN) ok = 0;
    }
    unsigned m = __ballot_sync(0xffffffffu, ok);
    if (lane == 0) g_is64 = (m == 0xffffffffu) ? 1 : 0;
}
__device__ __forceinline__ int edge_src(const void* ei, int e) {
    return g_is64 ? (int)((const long long*)ei)[e] : ((const int*)ei)[e];
}
__device__ __forceinline__ int edge_dst(const void* ei, int e) {
    return g_is64 ? (int)((const long long*)ei)[NE + e] : ((const int*)ei)[NE + e];
}

// ---------------------------------------------------------------------------
// CSR prologue
// ---------------------------------------------------------------------------
__global__ void zero_i(int* __restrict__ p, int n) {
    int i = blockIdx.x * blockDim.x + threadIdx.x;
    if (i < n) p[i] = 0;
}
__global__ void degree_k(const void* __restrict__ ei) {
    int e = blockIdx.x * blockDim.x + threadIdx.x;
    if (e < NE) atomicAdd(&g_deg[edge_dst(ei, e)], 1);
}
__global__ __launch_bounds__(SCAN_B) void bsum_k() {
    __shared__ int ws[SCAN_B / 32];
    int i = blockIdx.x * SCAN_B + threadIdx.x;
    int lane = threadIdx.x & 31, w = threadIdx.x >> 5;
    int v = (i < NN) ? g_deg[i] : 0;
    int s = v;
#pragma unroll
    for (int o = 16; o; o >>= 1) s += __shfl_xor_sync(0xffffffffu, s, o);
    if (lane == 0) ws[w] = s;
    __syncthreads();
    if (threadIdx.x == 0) {
        int tot = 0;
#pragma unroll
        for (int k = 0; k < SCAN_B / 32; k++) tot += ws[k];
        g_bsum[blockIdx.x] = tot;
    }
}
__global__ __launch_bounds__(256) void bscan_k() {
    __shared__ int ws[8];
    int t = threadIdx.x, lane = t & 31, w = t >> 5;
    int v = (t < NBLK) ? g_bsum[t] : 0;
    int incl = v;
#pragma unroll
    for (int o = 1; o < 32; o <<= 1) {
        int x = __shfl_up_sync(0xffffffffu, incl, o);
        if (lane >= o) incl += x;
    }
    if (lane == 31) ws[w] = incl;
    __syncthreads();
    if (w == 0 && lane < 8) {
        int wv = ws[lane];
        int wi = wv;
#pragma unroll
        for (int o = 1; o < 8; o <<= 1) {
            int x = __shfl_up_sync(0xffu, wi, o);
            if (lane >= o) wi += x;
        }
        ws[lane] = wi - wv;
    }
    __syncthreads();
    if (t < NBLK) g_boff[t] = incl - v + ws[w];
    if (t == 0) g_rowstart[NN] = NE;
}
__global__ __launch_bounds__(SCAN_B) void rowstart_k() {
    __shared__ int ws[SCAN_B / 32];
    int i = blockIdx.x * SCAN_B + threadIdx.x;
    int lane = threadIdx.x & 31, w = threadIdx.x >> 5;
    int v = (i < NN) ? g_deg[i] : 0;
    int incl = v;
#pragma unroll
    for (int o = 1; o < 32; o <<= 1) {
        int x = __shfl_up_sync(0xffffffffu, incl, o);
        if (lane >= o) incl += x;
    }
    if (lane == 31) ws[w] = incl;
    __syncthreads();
    if (w == 0 && lane < SCAN_B / 32) {
        int wv = ws[lane];
        int wi = wv;
#pragma unroll
        for (int o = 1; o < SCAN_B / 32; o <<= 1) {
            int x = __shfl_up_sync(0xffu, wi, o);
            if (lane >= o) wi += x;
        }
        ws[lane] = wi - wv;
    }
    __syncthreads();
    if (i < NN) {
        int excl = incl - v + ws[w] + g_boff[blockIdx.x];
        g_rowstart[i] = excl;
        g_cursor[i]   = excl;
        g_inv[i]      = 1.f / (float)(v > 1 ? v : 1);
    }
}
__global__ void fill_k(const void* __restrict__ ei) {
    int e = blockIdx.x * blockDim.x + threadIdx.x;
    if (e >= NE) return;
    int s = edge_src(ei, e);
    int d = edge_dst(ei, e);
    int pos = atomicAdd(&g_cursor[d], 1);
    g_csrc[pos] = s;
}

// ---------------------------------------------------------------------------
// Tensor-core batched GEMM via warp mma.sync (bf16-split, fp32 reg accum).
//   C[s][M x 128] = A[M x K] @ W[s]^T,  D = Ahi*Bhi + Ahi*Blo + Alo*Bhi
// 128x128 tile per CTA; 8 warps (4 row-groups x 2 col-groups); per warp
// 2 m16-tiles x 8 n8-tiles of m16n8k16. Tiles staged in padded row-major
// smem (PAD = 2*KS+16 -> ldmatrix row pointers are bank-conflict-free).
// ---------------------------------------------------------------------------
__global__ __launch_bounds__(256, 1)
void bgemm_mma(const float* __restrict__ A,
               const float* __restrict__ W0, const float* __restrict__ W1,
               const float* __restrict__ W2,
               float* __restrict__ C0, float* __restrict__ C1, float* __restrict__ C2,
               int M, int K)
{
    const float* W = (blockIdx.y == 0) ? W0 : (blockIdx.y == 1) ? W1 : W2;
    float*       C = (blockIdx.y == 0) ? C0 : (blockIdx.y == 1) ? C1 : C2;

    extern __shared__ __align__(16) char smem[];
    const int t     = threadIdx.x;
    const int wid   = t >> 5;
    const int lid   = t & 31;
    const int m0    = blockIdx.x * 128;
    const int steps = (K + 15) >> 4;
    const int KS    = steps * 16;
    const int PAD   = KS * 2 + 16;     // bytes per smem row
    const int TB    = 128 * PAD;

    char* AHI = smem;
    char* ALO = smem + TB;
    char* BHI = smem + 2 * TB;
    char* BLO = smem + 3 * TB;

    // Convert A -> bf16 hi/lo (rows >= M, cols >= K zeroed)
    for (int idx = t; idx < 128 * KS; idx += 256) {
        int row = idx / KS, k = idx - row * KS;
        int am = m0 + row;
        float a = (k < K && am < M) ? A[(size_t)am * K + k] : 0.f;
        __nv_bfloat16 hi = __float2bfloat16(a);
        __nv_bfloat16 lo = __float2bfloat16(a - __bfloat162float(hi));
        *(__nv_bfloat16*)(AHI + row * PAD + k * 2) = hi;
        *(__nv_bfloat16*)(ALO + row * PAD + k * 2) = lo;
    }
    // Convert W -> bf16 hi/lo (all 128 rows valid)
    for (int idx = t; idx < 128 * KS; idx += 256) {
        int row = idx / KS, k = idx - row * KS;
        float a = (k < K) ? W[(size_t)row * K + k] : 0.f;
        __nv_bfloat16 hi = __float2bfloat16(a);
        __nv_bfloat16 lo = __float2bfloat16(a - __bfloat162float(hi));
        *(__nv_bfloat16*)(BHI + row * PAD + k * 2) = hi;
        *(__nv_bfloat16*)(BLO + row * PAD + k * 2) = lo;
    }
    __syncthreads();

    const int wrow = wid >> 1;   // 0..3 : rows wrow*32 .. +31
    const int wcol = wid & 1;    // 0..1 : cols wcol*64 .. +63

    float acc[2][8][4];
#pragma unroll
    for (int mt = 0; mt < 2; mt++)
#pragma unroll
        for (int nt = 0; nt < 8; nt++)
#pragma unroll
            for (int i = 0; i < 4; i++) acc[mt][nt][i] = 0.f;

    const uint32_t ahi_b = smem_u32(AHI), alo_b = smem_u32(ALO);
    const uint32_t bhi_b = smem_u32(BHI), blo_b = smem_u32(BLO);

    // ldmatrix lane offsets
    const int a_row = (lid & 15);            // rows 0-15 of the m16 tile
    const int a_koff = (lid >> 4) * 16;      // k halves
    const int b_row = (lid & 7) + ((lid >> 4) & 1) * 8;  // n row within 16-pair
    const int b_koff = ((lid >> 3) & 1) * 16;

    for (int kc = 0; kc < steps; kc++) {
        const int kb = kc * 32;              // byte offset of this k16 chunk
        uint32_t ah[2][4], al[2][4], bh[4][4], bl[4][4];
#pragma unroll
        for (int mt = 0; mt < 2; mt++) {
            uint32_t off = (uint32_t)((wrow * 32 + mt * 16 + a_row) * PAD + kb + a_koff);
            ldsm4(ah[mt], ahi_b + off);
            ldsm4(al[mt], alo_b + off);
        }
#pragma unroll
        for (int p = 0; p < 4; p++) {
            uint32_t off = (uint32_t)((wcol * 64 + p * 16 + b_row) * PAD + kb + b_koff);
            ldsm4(bh[p], bhi_b + off);
            ldsm4(bl[p], blo_b + off);
        }
#pragma unroll
        for (int mt = 0; mt < 2; mt++)
#pragma unroll
            for (int nt = 0; nt < 8; nt++) {
                int p = nt >> 1, o = (nt & 1) * 2;
                mma_bf16(acc[mt][nt], ah[mt], bh[p][o], bh[p][o + 1]);  // Ahi*Bhi
                mma_bf16(acc[mt][nt], ah[mt], bl[p][o], bl[p][o + 1]);  // Ahi*Blo
                mma_bf16(acc[mt][nt], al[mt], bh[p][o], bh[p][o + 1]);  // Alo*Bhi
            }
    }

    // store: c frag lane mapping — rows l/4 and l/4+8, cols (l%4)*2, +1
#pragma unroll
    for (int mt = 0; mt < 2; mt++) {
        int r0 = m0 + wrow * 32 + mt * 16 + (lid >> 2);
        int r1 = r0 + 8;
#pragma unroll
        for (int nt = 0; nt < 8; nt++) {
            int c = wcol * 64 + nt * 8 + (lid & 3) * 2;
            if (r0 < M) *(float2*)&C[(size_t)r0 * 128 + c] = make_float2(acc[mt][nt][0], acc[mt][nt][1]);
            if (r1 < M) *(float2*)&C[(size_t)r1 * 128 + c] = make_float2(acc[mt][nt][2], acc[mt][nt][3]);
        }
    }
}

// ---------------------------------------------------------------------------
// Fused CSR aggregation + epilogue (unchanged from 444us version)
// ---------------------------------------------------------------------------
__global__ __launch_bounds__(256) void agg_epi_k(
    const float* __restrict__ y, const float* __restrict__ r,
    const float* __restrict__ res, const float* __restrict__ bl,
    const float* __restrict__ gam, const float* __restrict__ bet,
    const float* __restrict__ mu,  const float* __restrict__ var,
    float* __restrict__ h)
{
    long long gid = (long long)blockIdx.x * blockDim.x + threadIdx.x;
    int node = (int)(gid >> 5);
    if (node >= NN) return;
    int lane = threadIdx.x & 31;

    int beg = g_rowstart[node];
    int end = g_rowstart[node + 1];

    float4 acc = make_float4(0.f, 0.f, 0.f, 0.f);
    int j = beg;
    for (; j + 3 < end; j += 4) {
        int s0 = g_csrc[j];
        int s1 = g_csrc[j + 1];
        int s2 = g_csrc[j + 2];
        int s3 = g_csrc[j + 3];
        float4 v0 = ((const float4*)(y + (size_t)s0 * 128))[lane];
        float4 v1 = ((const float4*)(y + (size_t)s1 * 128))[lane];
        float4 v2 = ((const float4*)(y + (size_t)s2 * 128))[lane];
        float4 v3 = ((const float4*)(y + (size_t)s3 * 128))[lane];
        acc.x += (v0.x + v1.x) + (v2.x + v3.x);
        acc.y += (v0.y + v1.y) + (v2.y + v3.y);
        acc.z += (v0.z + v1.z) + (v2.z + v3.z);
        acc.w += (v0.w + v1.w) + (v2.w + v3.w);
    }
    for (; j < end; j++) {
        int s0 = g_csrc[j];
        float4 v0 = ((const float4*)(y + (size_t)s0 * 128))[lane];
        acc.x += v0.x; acc.y += v0.y; acc.z += v0.z; acc.w += v0.w;
    }

    float iv = g_inv[node];
    int c = lane * 4;
    size_t idx = (size_t)node * 128 + c;
    float4 blv  = *(const float4*)(bl  + c);
    float4 gamv = *(const float4*)(gam + c);
    float4 betv = *(const float4*)(bet + c);
    float4 muv  = *(const float4*)(mu  + c);
    float4 varv = *(const float4*)(var + c);
    float4 rv   = *(const float4*)(r   + idx);
    float4 resv = *(const float4*)(res + idx);

    float4 o;
    {
        float s0 = gamv.x * rsqrtf(varv.x + BN_EPS);
        float s1 = gamv.y * rsqrtf(varv.y + BN_EPS);
        float s2 = gamv.z * rsqrtf(varv.z + BN_EPS);
        float s3 = gamv.w * rsqrtf(varv.w + BN_EPS);
        float p0 = acc.x * iv + blv.x + rv.x;
        float p1 = acc.y * iv + blv.y + rv.y;
        float p2 = acc.z * iv + blv.z + rv.z;
        float p3 = acc.w * iv + blv.w + rv.w;
        o.x = fmaxf((p0 - muv.x) * s0 + betv.x, 0.f) + resv.x;
        o.y = fmaxf((p1 - muv.y) * s1 + betv.y, 0.f) + resv.y;
        o.z = fmaxf((p2 - muv.z) * s2 + betv.z, 0.f) + resv.z;
        o.w = fmaxf((p3 - muv.w) * s3 + betv.w, 0.f) + resv.w;
    }
    *(float4*)(h + idx) = o;
}

// ---------------------------------------------------------------------------
// Layer 2 kernels (unchanged)
// ---------------------------------------------------------------------------
__global__ void z2_k(const float* __restrict__ h, const float* __restrict__ Wl2) {
    long long gid = (long long)blockIdx.x * blockDim.x + threadIdx.x;
    int node = (int)(gid >> 5);
    if (node >= NN) return;
    int lane = threadIdx.x & 31;
    float4 hv = ((const float4*)(h + (size_t)node * 128))[lane];
    float4 w0 = ((const float4*)Wl2)[lane];
    float4 w1 = ((const float4*)(Wl2 + 128))[lane];
    float d0 = hv.x * w0.x + hv.y * w0.y + hv.z * w0.z + hv.w * w0.w;
    float d1 = hv.x * w1.x + hv.y * w1.y + hv.z * w1.z + hv.w * w1.w;
#pragma unroll
    for (int o = 16; o; o >>= 1) {
        d0 += __shfl_xor_sync(0xffffffffu, d0, o);
        d1 += __shfl_xor_sync(0xffffffffu, d1, o);
    }
    if (lane == 0) {
        g_z2[node * 2]     = d0;
        g_z2[node * 2 + 1] = d1;
    }
}

__global__ void out2_k(const float* __restrict__ h, const float* __restrict__ Wr2,
                       const float* __restrict__ bl2, float* __restrict__ out) {
    long long gid = (long long)blockIdx.x * blockDim.x + threadIdx.x;
    int node = (int)(gid >> 5);
    if (node >= NN) return;
    int lane = threadIdx.x & 31;

    float4 hv = ((const float4*)(h + (size_t)node * 128))[lane];
    float4 w0 = ((const float4*)Wr2)[lane];
    float4 w1 = ((const float4*)(Wr2 + 128))[lane];
    float d0 = hv.x * w0.x + hv.y * w0.y + hv.z * w0.z + hv.w * w0.w;
    float d1 = hv.x * w1.x + hv.y * w1.y + hv.z * w1.z + hv.w * w1.w;

    int beg = g_rowstart[node];
    int end = g_rowstart[node + 1];
    float a0 = 0.f, a1 = 0.f;
    for (int j = beg + lane; j < end; j += 32) {
        int s = g_csrc[j];
        float2 v = ((const float2*)g_z2)[s];
        a0 += v.x; a1 += v.y;
    }
#pragma unroll
    for (int o = 16; o; o >>= 1) {
        d0 += __shfl_xor_sync(0xffffffffu, d0, o);
        d1 += __shfl_xor_sync(0xffffffffu, d1, o);
        a0 += __shfl_xor_sync(0xffffffffu, a0, o);
        a1 += __shfl_xor_sync(0xffffffffu, a1, o);
    }
    if (lane == 0) {
        float iv = g_inv[node];
        out[node * 2]     = a0 * iv + bl2[0] + d0;
        out[node * 2 + 1] = a1 * iv + bl2[1] + d1;
    }
}

// ---------------------------------------------------------------------------
// Launch
// ---------------------------------------------------------------------------
extern "C" void kernel_launch(void* const* d_in, const int* in_sizes, int n_in,
                              void* d_out, int out_size)
{
    const float* x     = (const float*)d_in[0];
    const void*  ei    = d_in[1];
    const float* Wl0   = (const float*)d_in[2];
    const float* bl0   = (const float*)d_in[3];
    const float* Wr0   = (const float*)d_in[4];
    const float* Wl1   = (const float*)d_in[5];
    const float* bl1   = (const float*)d_in[6];
    const float* Wr1   = (const float*)d_in[7];
    const float* Wl2   = (const float*)d_in[8];
    const float* bl2   = (const float*)d_in[9];
    const float* Wr2   = (const float*)d_in[10];
    const float* Wres0 = (const float*)d_in[11];
    const float* bn0g  = (const float*)d_in[12];
    const float* bn0b  = (const float*)d_in[13];
    const float* bn0m  = (const float*)d_in[14];
    const float* bn0v  = (const float*)d_in[15];
    const float* bn1g  = (const float*)d_in[16];
    const float* bn1b  = (const float*)d_in[17];
    const float* bn1m  = (const float*)d_in[18];
    const float* bn1v  = (const float*)d_in[19];
    float* out = (float*)d_out;

    float *y, *r, *p, *h0, *h1;
    int* deg;
    cudaGetSymbolAddress((void**)&y,   g_y);
    cudaGetSymbolAddress((void**)&r,   g_r);
    cudaGetSymbolAddress((void**)&p,   g_p);
    cudaGetSymbolAddress((void**)&h0,  g_h0);
    cudaGetSymbolAddress((void**)&h1,  g_h1);
    cudaGetSymbolAddress((void**)&deg, g_deg);

    // Idempotent, called every launch (no static guards allowed).
    cudaFuncSetAttribute(bgemm_mma, cudaFuncAttributeMaxDynamicSharedMemorySize, GEMM_SMEM);

    const int T = 256;
    const int gemm_bx = (NN + 127) / 128;                     // 391
    const int node_warp_blocks = (NN * 32 + T - 1) / T;       // 6250

    // ----- CSR build -----
    detect_k<<<1, 32>>>(ei);
    zero_i<<<(NN + T - 1) / T, T>>>(deg, NN);
    degree_k<<<(NE + T - 1) / T, T>>>(ei);
    bsum_k<<<NBLK, SCAN_B>>>();
    bscan_k<<<1, 256>>>();
    rowstart_k<<<NBLK, SCAN_B>>>();
    fill_k<<<(NE + T - 1) / T, T>>>(ei);

    // ----- layer 0: 3 tensor GEMMs in one launch, then fused agg+BN+ReLU+res -----
    bgemm_mma<<<dim3(gemm_bx, 3), T, GEMM_SMEM>>>(x, Wl0, Wr0, Wres0, y, r, p, NN, KIN);
    agg_epi_k<<<node_warp_blocks, T>>>(y, r, p, bl0, bn0g, bn0b, bn0m, bn0v, h0);

    // ----- layer 1 -----
    bgemm_mma<<<dim3(gemm_bx, 2), T, GEMM_SMEM>>>(h0, Wl1, Wr1, Wr1, y, r, r, NN, HID);
    agg_epi_k<<<node_warp_blocks, T>>>(y, r, h0, bl1, bn1g, bn1b, bn1m, bn1v, h1);

    // ----- layer 2 -----
    z2_k<<<node_warp_blocks, T>>>(h1, Wl2);
    out2_k<<<node_warp_blocks, T>>>(h1, Wr2, bl2, out);
}